// round 1
// baseline (speedup 1.0000x reference)
#include <cuda_runtime.h>

// Precomputed uniform weight constants:
//   g_prec[0..3]  = 0.5 * weights[0][i]   (fused into data angle half)
//   g_prec[4..7]  = cos(0.5 * weights[1][i])
//   g_prec[8..11] = sin(0.5 * weights[1][i])
__device__ float g_prec[12];

__global__ void precompute_kernel(const float* __restrict__ w) {
    int i = threadIdx.x;
    if (i < 4) {
        g_prec[i] = 0.5f * w[i];           // layer-0 half-angles
        float h = 0.5f * w[4 + i];         // layer-1 half-angles
        g_prec[4 + i] = cosf(h);
        g_prec[8 + i] = sinf(h);
    }
}

// CNOT(ctrl, ctrl+1) on a 16-amplitude register statevector.
// Index layout: k = b0*8 + b1*4 + b2*2 + b3 (wire 0 = MSB).
// Pure compile-time permutation -> zero SASS cost after unroll.
template <int CTRL>
__device__ __forceinline__ void cnot(float a[16]) {
    constexpr int cs = 8 >> CTRL;       // control-bit stride
    constexpr int ts = cs >> 1;         // target-bit stride
#pragma unroll
    for (int k = 0; k < 16; k++) {
        if ((k & cs) && !(k & ts)) {
            float tmp = a[k];
            a[k] = a[k + ts];
            a[k + ts] = tmp;
        }
    }
}

// RY(theta) on wire W; c = cos(theta/2), s = sin(theta/2). Real rotation.
template <int W>
__device__ __forceinline__ void ry(float a[16], float c, float s) {
    constexpr int st = 8 >> W;
#pragma unroll
    for (int k = 0; k < 16; k++) {
        if (!(k & st)) {
            float a0 = a[k];
            float a1 = a[k + st];
            a[k]      = fmaf(c, a0, -s * a1);
            a[k + st] = fmaf(s, a0,  c * a1);
        }
    }
}

__global__ __launch_bounds__(256)
void qsim_kernel(const float4* __restrict__ x, float4* __restrict__ out, int n) {
    int tid = blockIdx.x * blockDim.x + threadIdx.x;
    if (tid >= n) return;

    // Broadcast uniform weight constants (L1-resident after first warp).
    float w0h[4], C1[4], S1[4];
#pragma unroll
    for (int i = 0; i < 4; i++) {
        w0h[i] = g_prec[i];
        C1[i]  = g_prec[4 + i];
        S1[i]  = g_prec[8 + i];
    }

    float4 xv = x[tid];

    // Fused data + layer-0 RY: half-angle = 0.5*x_i + 0.5*w0_i
    float c[4], s[4];
    {
        float h;
        h = fmaf(0.5f, xv.x, w0h[0]); __sincosf(h, &s[0], &c[0]);
        h = fmaf(0.5f, xv.y, w0h[1]); __sincosf(h, &s[1], &c[1]);
        h = fmaf(0.5f, xv.z, w0h[2]); __sincosf(h, &s[2], &c[2]);
        h = fmaf(0.5f, xv.w, w0h[3]); __sincosf(h, &s[3], &c[3]);
    }

    // Product state |psi> = (c0,s0) x (c1,s1) x (c2,s2) x (c3,s3)  (28 MULs)
    float a[16];
    {
        float t01[4];
        t01[0] = c[0] * c[1]; t01[1] = c[0] * s[1];
        t01[2] = s[0] * c[1]; t01[3] = s[0] * s[1];
        float t012[8];
#pragma unroll
        for (int j = 0; j < 4; j++) {
            t012[2 * j]     = t01[j] * c[2];
            t012[2 * j + 1] = t01[j] * s[2];
        }
#pragma unroll
        for (int j = 0; j < 8; j++) {
            a[2 * j]     = t012[j] * c[3];
            a[2 * j + 1] = t012[j] * s[3];
        }
    }

    // Layer 1 entangler
    cnot<0>(a); cnot<1>(a); cnot<2>(a);

    // Layer 2: uniform-angle RYs
    ry<0>(a, C1[0], S1[0]);
    ry<1>(a, C1[1], S1[1]);
    ry<2>(a, C1[2], S1[2]);
    ry<3>(a, C1[3], S1[3]);

    // Layer 2 entangler
    cnot<0>(a); cnot<1>(a); cnot<2>(a);

    // probs + signed reductions: E_w = sum_k (-1)^{bit_w(k)} * a_k^2
    float p[16];
#pragma unroll
    for (int k = 0; k < 16; k++) p[k] = a[k] * a[k];

    float s3[8];                 // summed over wire 3 (LSB)
    float e3 = 0.0f;
#pragma unroll
    for (int j = 0; j < 8; j++) {
        s3[j] = p[2 * j] + p[2 * j + 1];
        e3   += p[2 * j] - p[2 * j + 1];
    }
    float s2[4];
    float e2 = 0.0f;
#pragma unroll
    for (int j = 0; j < 4; j++) {
        s2[j] = s3[2 * j] + s3[2 * j + 1];
        e2   += s3[2 * j] - s3[2 * j + 1];
    }
    float s1a = s2[0] + s2[1];
    float s1b = s2[2] + s2[3];
    float e1  = (s2[0] - s2[1]) + (s2[2] - s2[3]);
    float e0  = s1a - s1b;

    out[tid] = make_float4(e0, e1, e2, e3);
}

extern "C" void kernel_launch(void* const* d_in, const int* in_sizes, int n_in,
                              void* d_out, int out_size) {
    const float* x = (const float*)d_in[0];       // [B, 4] float32
    const float* w = (const float*)d_in[1];       // [2, 4] float32
    float* out = (float*)d_out;                   // [B, 4] float32

    int n = in_sizes[0] / 4;                      // batch size

    precompute_kernel<<<1, 32>>>(w);

    int block = 256;
    int grid = (n + block - 1) / block;
    qsim_kernel<<<grid, block>>>((const float4*)x, (float4*)out, n);
}

// round 2
// speedup vs baseline: 1.3821x; 1.3821x over previous
#include <cuda_runtime.h>

// Uniform precomputed constants:
//   g_prec[0..3]   = w0_i  (layer-0 weight angles, added to data angle: theta_i = x_i + w0_i)
//   g_prec[4..22]  = 19 Heisenberg coefficients (products of cos/sin(w1_i))
// Derivation: M_w = C† R1† C† Z_w C R1 C expanded in Pauli strings; Y-strings
// vanish on the real product state; <Z_i>=cos(theta_i), <X_i>=sin(theta_i).
__device__ float g_prec[23];

__global__ void precompute_kernel(const float* __restrict__ w) {
    if (threadIdx.x == 0) {
        float C[4], S[4];
#pragma unroll
        for (int i = 0; i < 4; i++) {
            g_prec[i] = w[i];                 // w0_i (full angle)
            C[i] = cosf(w[4 + i]);            // C_i' = cos(w1_i)
            S[i] = sinf(w[4 + i]);            // S_i' = sin(w1_i)
        }
        float* g = g_prec + 4;
        // E0 = a0*C0 + a1*S0S1
        g[0]  =  C[0];
        g[1]  = -S[0];
        // E1 = b0*C1 + b1*C0*S1S2 + b2*S0S2
        g[2]  =  C[0] * C[1];
        g[3]  = -C[0] * S[1];
        g[4]  =  S[0] * S[1];
        // E2 = c0*C0C2 + c1*C1S2S3 + c2*C0S1S3 + c3*S0S1C2 + c4*S0S3
        g[5]  =  C[0] * C[1] * C[2];
        g[6]  = -C[0] * C[1] * S[2];
        g[7]  =  C[0] * S[1] * S[2];
        g[8]  = -S[0] * C[1] * C[2];
        g[9]  = -S[0] * S[1] * S[2];
        // E3 = d0*C1C3 + d1*C0C2S3 + d2*C1S2 + d3*C0S1S2C3
        //    + d4*C0S1 + d5*S0S1C2S3 + d6*S0S2C3 + d7*S0
        g[10] =  C[0] * C[1] * C[2] * C[3];
        g[11] = -C[0] * C[1] * C[2] * S[3];
        g[12] =  C[0] * C[1] * S[2] * S[3];
        g[13] = -C[0] * S[1] * C[2] * C[3];
        g[14] = -C[0] * S[1] * S[2] * S[3];
        g[15] =  S[0] * C[1] * C[2] * S[3];
        g[16] =  S[0] * S[1] * C[2] * C[3];
        g[17] =  S[0] * S[1] * S[2] * S[3];
        g[18] = 0.0f; // pad
    }
}

__global__ __launch_bounds__(256)
void qsim_kernel(const float4* __restrict__ x, float4* __restrict__ out, int n) {
    int tid = blockIdx.x * blockDim.x + threadIdx.x;
    if (tid >= n) return;

    // Broadcast uniform constants (L1/L2 resident).
    float w0[4], g[18];
#pragma unroll
    for (int i = 0; i < 4; i++) w0[i] = g_prec[i];
#pragma unroll
    for (int i = 0; i < 18; i++) g[i] = g_prec[4 + i];

    float4 xv = x[tid];

    float C0, S0, C1, S1, C2, S2, C3, S3;
    __sincosf(xv.x + w0[0], &S0, &C0);
    __sincosf(xv.y + w0[1], &S1, &C1);
    __sincosf(xv.z + w0[2], &S2, &C2);
    __sincosf(xv.w + w0[3], &S3, &C3);

    // Shared subproducts
    float s0s1 = S0 * S1;
    float s1s2 = S1 * S2;
    float s0s2 = S0 * S2;
    float s2s3 = S2 * S3;
    float c0s1 = C0 * S1;
    float c0c2 = C0 * C2;
    float s0s3 = S0 * S3;
    float s2c3 = S2 * C3;
    float c2s3 = C2 * S3;

    // E0 = a0*C0 + a1*S0S1
    float e0 = fmaf(g[0], C0, g[1] * s0s1);

    // E1 = b0*C1 + b1*C0*S1S2 + b2*S0S2
    float e1 = fmaf(g[2], C1, fmaf(g[3] * C0, s1s2, g[4] * s0s2));

    // E2 = c0*C0C2 + c1*C1*S2S3 + c2*C0S1*S3 + c3*S0S1*C2 + c4*S0S3
    float e2 = g[5] * c0c2;
    e2 = fmaf(g[6] * C1, s2s3, e2);
    e2 = fmaf(g[7] * c0s1, S3, e2);
    e2 = fmaf(g[8] * s0s1, C2, e2);
    e2 = fmaf(g[9], s0s3, e2);

    // E3 = d0*C1*C3 + d1*C0C2*S3 + d2*C1*S2 + d3*C0S1*S2C3
    //    + d4*C0S1 + d5*S0S1*C2S3 + d6*S0*S2C3 + d7*S0
    float e3 = g[10] * C1 * C3;
    e3 = fmaf(g[11] * c0c2, S3, e3);
    e3 = fmaf(g[12] * C1, S2, e3);
    e3 = fmaf(g[13] * c0s1, s2c3, e3);
    e3 = fmaf(g[14], c0s1, e3);
    e3 = fmaf(g[15] * s0s1, c2s3, e3);
    e3 = fmaf(g[16] * S0, s2c3, e3);
    e3 = fmaf(g[17], S0, e3);

    out[tid] = make_float4(e0, e1, e2, e3);
}

extern "C" void kernel_launch(void* const* d_in, const int* in_sizes, int n_in,
                              void* d_out, int out_size) {
    const float* x = (const float*)d_in[0];       // [B, 4] float32
    const float* w = (const float*)d_in[1];       // [2, 4] float32
    float* out = (float*)d_out;                   // [B, 4] float32

    int n = in_sizes[0] / 4;                      // batch size

    precompute_kernel<<<1, 32>>>(w);

    int block = 256;
    int grid = (n + block - 1) / block;
    qsim_kernel<<<grid, block>>>((const float4*)x, (float4*)out, n);
}

// round 3
// speedup vs baseline: 1.7085x; 1.2362x over previous
#include <cuda_runtime.h>

// Heisenberg-picture closed form:
//   theta_i = x_i + w0_i;  c_i = cos(theta_i), s_i = sin(theta_i)
//   C_i = cos(w1_i), S_i = sin(w1_i)
//   E_w = sum of Pauli-string expectations (Y-strings vanish on real states).
// All weight-dependent coefficients are computed per-thread (uniform -> cheap,
// amortized over 2 batch elements per thread; no second kernel, no global
// scratch, no inter-kernel graph dependency).

struct Coeffs {
    float g[18];
};

__device__ __forceinline__ float4 eval_elem(float4 xv, float4 w0, const Coeffs& k) {
    float C0, S0, C1, S1, C2, S2, C3, S3;
    __sincosf(xv.x + w0.x, &S0, &C0);
    __sincosf(xv.y + w0.y, &S1, &C1);
    __sincosf(xv.z + w0.z, &S2, &C2);
    __sincosf(xv.w + w0.w, &S3, &C3);

    // Shared subproducts
    float s0s1 = S0 * S1;
    float s1s2 = S1 * S2;
    float s0s2 = S0 * S2;
    float s2s3 = S2 * S3;
    float c0s1 = C0 * S1;
    float c0c2 = C0 * C2;
    float s0s3 = S0 * S3;
    float s2c3 = S2 * C3;
    float c2s3 = C2 * S3;

    const float* g = k.g;

    float e0 = fmaf(g[0], C0, g[1] * s0s1);

    float e1 = fmaf(g[2], C1, fmaf(g[3] * C0, s1s2, g[4] * s0s2));

    float e2 = g[5] * c0c2;
    e2 = fmaf(g[6] * C1, s2s3, e2);
    e2 = fmaf(g[7] * c0s1, S3, e2);
    e2 = fmaf(g[8] * s0s1, C2, e2);
    e2 = fmaf(g[9], s0s3, e2);

    float e3 = g[10] * C1 * C3;
    e3 = fmaf(g[11] * c0c2, S3, e3);
    e3 = fmaf(g[12] * C1, S2, e3);
    e3 = fmaf(g[13] * c0s1, s2c3, e3);
    e3 = fmaf(g[14], c0s1, e3);
    e3 = fmaf(g[15] * s0s1, c2s3, e3);
    e3 = fmaf(g[16] * S0, s2c3, e3);
    e3 = fmaf(g[17], S0, e3);

    return make_float4(e0, e1, e2, e3);
}

__global__ __launch_bounds__(256)
void qsim_kernel(const float4* __restrict__ x, const float4* __restrict__ w,
                 float4* __restrict__ out, int n_half, int n) {
    int tid = blockIdx.x * blockDim.x + threadIdx.x;
    if (tid >= n_half) return;

    // Front-batch all global loads (MLP): two data elements + weights.
    float4 xa = x[tid];
    int ib = tid + n_half;
    bool has_b = ib < n;
    float4 xb = has_b ? x[ib] : xa;
    float4 w0 = w[0];      // layer-0 weight angles (warp-uniform, L1 broadcast)
    float4 w1 = w[1];      // layer-1 weight angles

    // Weight trig + Heisenberg coefficients (uniform; amortized over 2 elems).
    float C[4], S[4];
    __sincosf(w1.x, &S[0], &C[0]);
    __sincosf(w1.y, &S[1], &C[1]);
    __sincosf(w1.z, &S[2], &C[2]);
    __sincosf(w1.w, &S[3], &C[3]);

    Coeffs k;
    // E0 terms
    k.g[0]  =  C[0];
    k.g[1]  = -S[0];
    // E1 terms
    float c0c1 = C[0] * C[1];
    float c0s1 = C[0] * S[1];
    float s0c1 = S[0] * C[1];
    float s0s1 = S[0] * S[1];
    k.g[2]  =  c0c1;
    k.g[3]  = -c0s1;
    k.g[4]  =  s0s1;
    // E2 terms
    k.g[5]  =  c0c1 * C[2];
    k.g[6]  = -c0c1 * S[2];
    k.g[7]  =  c0s1 * S[2];
    k.g[8]  = -s0c1 * C[2];
    k.g[9]  = -s0s1 * S[2];
    // E3 terms
    k.g[10] =  k.g[5] * C[3];
    k.g[11] = -k.g[5] * S[3];
    k.g[12] = -k.g[6] * S[3];
    k.g[13] = -c0s1 * C[2] * C[3];
    k.g[14] = -c0s1 * S[2] * S[3];
    k.g[15] = -k.g[8] * S[3];
    k.g[16] =  s0s1 * C[2] * C[3];
    k.g[17] = -k.g[9] * S[3];

    float4 ea = eval_elem(xa, w0, k);
    out[tid] = ea;
    if (has_b) {
        float4 eb = eval_elem(xb, w0, k);
        out[ib] = eb;
    }
}

extern "C" void kernel_launch(void* const* d_in, const int* in_sizes, int n_in,
                              void* d_out, int out_size) {
    const float4* x = (const float4*)d_in[0];     // [B, 4] float32
    const float4* w = (const float4*)d_in[1];     // [2, 4] float32
    float4* out = (float4*)d_out;                 // [B, 4] float32

    int n = in_sizes[0] / 4;                      // batch size
    int n_half = (n + 1) / 2;

    int block = 256;
    int grid = (n_half + block - 1) / block;
    qsim_kernel<<<grid, block>>>(x, w, out, n_half, n);
}